// round 1
// baseline (speedup 1.0000x reference)
#include <cuda_runtime.h>
#include <math.h>

#define DIMC 256
#define NTOK 128
#define BAT  8
#define HID  1024
#define EPSV 1e-5f
#define SAS  258   // sAttn row stride (floats) -- %4==2 to dodge 8-row bank conflicts
#define SATS 17    // sAt row stride

// -------- device scratch (no allocs allowed) --------
__device__ float g_x1 [BAT*NTOK*DIMC];
__device__ float g_q  [BAT*NTOK*DIMC];
__device__ float g_k  [BAT*NTOK*DIMC];
__device__ float g_v  [BAT*NTOK*DIMC];
__device__ float g_agg[BAT*NTOK*DIMC];
__device__ float g_h  [(size_t)BAT*NTOK*NTOK*HID];   // 512 MB hidden scratch

// ======================= Kernel 1: LN1 + q/k/v =======================
__global__ __launch_bounds__(256) void node_pre_kernel(
    const float* __restrict__ x,
    const float* __restrict__ Wq, const float* __restrict__ bq,
    const float* __restrict__ Wk, const float* __restrict__ bk,
    const float* __restrict__ Wv, const float* __restrict__ bv,
    const float* __restrict__ ln1s, const float* __restrict__ ln1b)
{
    __shared__ float sx[4][DIMC];
    int tid = threadIdx.x;
    int row0 = blockIdx.x * 4;
    int w = tid >> 5, lane = tid & 31;
    if (w < 4) {
        const float* xr = x + (size_t)(row0 + w) * DIMC;
        float vals[8], s = 0.f, sq = 0.f;
        #pragma unroll
        for (int u = 0; u < 8; u++) { vals[u] = xr[lane + u*32]; s += vals[u]; sq += vals[u]*vals[u]; }
        #pragma unroll
        for (int o = 16; o > 0; o >>= 1) { s += __shfl_xor_sync(~0u, s, o); sq += __shfl_xor_sync(~0u, sq, o); }
        float mean = s * (1.f/DIMC);
        float rstd = rsqrtf(sq * (1.f/DIMC) - mean*mean + EPSV);
        #pragma unroll
        for (int u = 0; u < 8; u++) {
            int c = lane + u*32;
            float v = (vals[u] - mean) * rstd * ln1s[c] + ln1b[c];
            sx[w][c] = v;
            g_x1[(row0 + w)*DIMC + c] = v;
        }
    }
    __syncthreads();
    int c = tid;
    float aq[4] = {}, ak[4] = {}, av[4] = {};
    for (int k = 0; k < DIMC; k++) {
        float wq = Wq[k*DIMC + c], wk = Wk[k*DIMC + c], wv = Wv[k*DIMC + c];
        #pragma unroll
        for (int r = 0; r < 4; r++) {
            float xv = sx[r][k];
            aq[r] += xv*wq; ak[r] += xv*wk; av[r] += xv*wv;
        }
    }
    #pragma unroll
    for (int r = 0; r < 4; r++) {
        g_q[(row0+r)*DIMC + c] = aq[r] + bq[c];
        g_k[(row0+r)*DIMC + c] = ak[r] + bk[c];
        g_v[(row0+r)*DIMC + c] = av[r] + bv[c];
    }
}

// ======================= GEMM micro-helpers =======================
__device__ __forceinline__ void stage_A16(float* sAt, const float* __restrict__ src,
                                          int lds, int kbase, int tid)
{
    #pragma unroll
    for (int it = 0; it < 8; it++) {
        int l = tid + it*256;
        int j = l >> 4, kk = l & 15;
        sAt[j*SATS + kk] = src[(size_t)j*lds + kbase + kk];
    }
}
__device__ __forceinline__ void stage_B16(float* sBt, const float* __restrict__ W,
                                          int ldw, int kbase, int cbase, int tid)
{
    #pragma unroll
    for (int it = 0; it < 8; it++) {
        int l = tid + it*256;
        int kk = l >> 7, cc = l & 127;
        sBt[kk*NTOK + cc] = W[(size_t)(kbase + kk)*ldw + cbase + cc];
    }
}
__device__ __forceinline__ void fma_At(const float* sAt, const float* sBt,
                                       int r0, int c0, float acc[8][8])
{
    #pragma unroll
    for (int kk = 0; kk < 16; kk++) {
        float a[8], bb[8];
        #pragma unroll
        for (int u = 0; u < 8; u++) a[u] = sAt[(r0+u)*SATS + kk];
        #pragma unroll
        for (int v = 0; v < 8; v++) bb[v] = sBt[kk*NTOK + c0 + v];
        #pragma unroll
        for (int u = 0; u < 8; u++)
            #pragma unroll
            for (int v = 0; v < 8; v++) acc[u][v] += a[u]*bb[v];
    }
}
__device__ __forceinline__ void fma_Attn(const float* sAttn, const float* sBt,
                                         int r0, int c0, int kbase, float acc[8][8])
{
    #pragma unroll
    for (int kk = 0; kk < 16; kk++) {
        float a[8], bb[8];
        #pragma unroll
        for (int u = 0; u < 8; u++) a[u] = sAttn[(r0+u)*SAS + kbase + kk];
        #pragma unroll
        for (int v = 0; v < 8; v++) bb[v] = sBt[kk*NTOK + c0 + v];
        #pragma unroll
        for (int u = 0; u < 8; u++)
            #pragma unroll
            for (int v = 0; v < 8; v++) acc[u][v] += a[u]*bb[v];
    }
}
#define ZERO_ACC(acc) { _Pragma("unroll") for (int u=0;u<8;u++) _Pragma("unroll") for (int v=0;v<8;v++) acc[u][v]=0.f; }

// ======================= Kernel 2: edge mega-kernel =======================
__global__ __launch_bounds__(256, 1) void edge_kernel(
    const float* __restrict__ y,
    const float* __restrict__ We,  const float* __restrict__ be,
    const float* __restrict__ Woe, const float* __restrict__ boe,
    const float* __restrict__ w1,  const float* __restrict__ b1,
    const float* __restrict__ w2,  const float* __restrict__ b2,
    const float* __restrict__ ln4s, const float* __restrict__ ln4b,
    const float* __restrict__ ln6s, const float* __restrict__ ln6b,
    float* __restrict__ yout)
{
    extern __shared__ float sm[];
    float* sAttn = sm;                        // 128 * SAS
    float* sTmp  = sAttn + NTOK*SAS;          // 128 * 128
    float* sAt   = sTmp  + NTOK*NTOK;         // 128 * SATS
    float* sBt   = sAt   + NTOK*SATS;         // 16 * 128
    float* sQ    = sBt   + 16*NTOK;           // 256

    int tid = threadIdx.x;
    int bi  = blockIdx.x;
    int b   = bi >> 7;
    int tx = tid & 15, ty = tid >> 4;
    int r0 = ty * 8, c0 = tx * 8;

    const float* yblk = y + (size_t)bi * NTOK * DIMC;
    size_t hbase = (size_t)bi * NTOK * HID;

    sQ[tid] = g_q[bi*DIMC + tid];

    float acc[8][8];

    // ---- GEMM1: e = y @ We + be ; attn = q*k/sqrt(dk)*(e+1)*e -> sAttn ----
    for (int ct = 0; ct < 2; ct++) {
        ZERO_ACC(acc);
        for (int kt = 0; kt < DIMC/16; kt++) {
            __syncthreads();
            stage_A16(sAt, yblk, DIMC, kt*16, tid);
            stage_B16(sBt, We, DIMC, kt*16, ct*128, tid);
            __syncthreads();
            fma_At(sAt, sBt, r0, c0, acc);
        }
        #pragma unroll
        for (int u = 0; u < 8; u++) {
            int j = r0 + u;
            #pragma unroll
            for (int v = 0; v < 8; v++) {
                int c = ct*128 + c0 + v;
                float e = acc[u][v] + be[c];
                float kv = g_k[(b*NTOK + j)*DIMC + c];
                sAttn[j*SAS + c] = sQ[c]*kv*0.17677669529663687f * (e + 1.f) * e;
            }
        }
    }
    __syncthreads();

    // ---- softmax over j (CTA-local) + agg = sum_j p*v ----
    {
        int c = tid;
        float m = -1e30f;
        for (int j = 0; j < NTOK; j++) m = fmaxf(m, sAttn[j*SAS + c]);
        float s = 0.f, aggv = 0.f;
        for (int j = 0; j < NTOK; j++) {
            float p = __expf(sAttn[j*SAS + c] - m);
            s += p;
            aggv += p * g_v[(b*NTOK + j)*DIMC + c];
        }
        g_agg[bi*DIMC + c] = aggv / s;
    }

    // ---- GEMM2: edge_out = attn @ Woe + boe ; + y residual ----
    for (int ct = 0; ct < 2; ct++) {
        ZERO_ACC(acc);
        for (int kt = 0; kt < DIMC/16; kt++) {
            __syncthreads();
            stage_B16(sBt, Woe, DIMC, kt*16, ct*128, tid);
            __syncthreads();
            fma_Attn(sAttn, sBt, r0, c0, kt*16, acc);
        }
        __syncthreads();  // all reads of sAttn done before overwriting (ct==1)
        #pragma unroll
        for (int u = 0; u < 8; u++) {
            int j = r0 + u;
            #pragma unroll
            for (int v = 0; v < 8; v++) {
                int c = ct*128 + c0 + v;
                float val = acc[u][v] + boe[c] + yblk[(size_t)j*DIMC + c];
                if (ct == 0) sTmp[j*NTOK + c0 + v] = val;
                else         sAttn[j*SAS + c] = val;
            }
        }
    }
    __syncthreads();
    for (int l = tid; l < NTOK*NTOK; l += 256) {
        int j = l >> 7, c = l & 127;
        sAttn[j*SAS + c] = sTmp[l];
    }
    __syncthreads();

    // ---- LN4 -> y2 (in place in sAttn) ----
    {
        int w = tid >> 5, lane = tid & 31;
        for (int j = w; j < NTOK; j += 8) {
            float s = 0.f, sq = 0.f;
            #pragma unroll
            for (int u = 0; u < 8; u++) {
                float v = sAttn[j*SAS + lane + u*32];
                s += v; sq += v*v;
            }
            #pragma unroll
            for (int o = 16; o > 0; o >>= 1) { s += __shfl_xor_sync(~0u,s,o); sq += __shfl_xor_sync(~0u,sq,o); }
            float mean = s * (1.f/256.f);
            float rstd = rsqrtf(sq*(1.f/256.f) - mean*mean + EPSV);
            #pragma unroll
            for (int u = 0; u < 8; u++) {
                int c = lane + u*32;
                float v = sAttn[j*SAS + c];
                sAttn[j*SAS + c] = (v - mean)*rstd*ln4s[c] + ln4b[c];
            }
        }
    }
    __syncthreads();

    // ---- GEMM3: h = relu(y2 @ w1 + b1) -> g_h ----
    for (int ht = 0; ht < HID/128; ht++) {
        ZERO_ACC(acc);
        for (int kt = 0; kt < DIMC/16; kt++) {
            __syncthreads();
            stage_B16(sBt, w1, HID, kt*16, ht*128, tid);
            __syncthreads();
            fma_Attn(sAttn, sBt, r0, c0, kt*16, acc);
        }
        #pragma unroll
        for (int u = 0; u < 8; u++) {
            int j = r0 + u;
            #pragma unroll
            for (int v = 0; v < 8; v++) {
                int hc = ht*128 + c0 + v;
                g_h[hbase + (size_t)j*HID + hc] = fmaxf(acc[u][v] + b1[hc], 0.f);
            }
        }
    }

    // ---- GEMM4: mlp = h @ w2 + b2 ; + y2 ; in place in sAttn ----
    for (int ct = 0; ct < 2; ct++) {
        ZERO_ACC(acc);
        for (int kt = 0; kt < HID/16; kt++) {
            __syncthreads();
            stage_A16(sAt, g_h + hbase, HID, kt*16, tid);
            stage_B16(sBt, w2, DIMC, kt*16, ct*128, tid);
            __syncthreads();
            fma_At(sAt, sBt, r0, c0, acc);
        }
        #pragma unroll
        for (int u = 0; u < 8; u++) {
            int j = r0 + u;
            #pragma unroll
            for (int v = 0; v < 8; v++) {
                int c = ct*128 + c0 + v;
                sAttn[j*SAS + c] = acc[u][v] + b2[c] + sAttn[j*SAS + c];
            }
        }
    }
    __syncthreads();

    // ---- LN6 -> y_out ----
    {
        int w = tid >> 5, lane = tid & 31;
        float* outblk = yout + (size_t)bi * NTOK * DIMC;
        for (int j = w; j < NTOK; j += 8) {
            float s = 0.f, sq = 0.f;
            #pragma unroll
            for (int u = 0; u < 8; u++) {
                float v = sAttn[j*SAS + lane + u*32];
                s += v; sq += v*v;
            }
            #pragma unroll
            for (int o = 16; o > 0; o >>= 1) { s += __shfl_xor_sync(~0u,s,o); sq += __shfl_xor_sync(~0u,sq,o); }
            float mean = s * (1.f/256.f);
            float rstd = rsqrtf(sq*(1.f/256.f) - mean*mean + EPSV);
            #pragma unroll
            for (int u = 0; u < 8; u++) {
                int c = lane + u*32;
                float v = sAttn[j*SAS + c];
                outblk[(size_t)j*DIMC + c] = (v - mean)*rstd*ln6s[c] + ln6b[c];
            }
        }
    }
}

// ======================= Kernel 3: node path finish =======================
__global__ __launch_bounds__(256) void node_post_kernel(
    const float* __restrict__ Won, const float* __restrict__ bon,
    const float* __restrict__ w1,  const float* __restrict__ b1,
    const float* __restrict__ w2,  const float* __restrict__ b2,
    const float* __restrict__ ln3s, const float* __restrict__ ln3b,
    const float* __restrict__ ln5s, const float* __restrict__ ln5b,
    float* __restrict__ xout)
{
    __shared__ float sx2[8][DIMC];
    __shared__ float sh[8][HID];
    int tid = threadIdx.x;
    int row0 = blockIdx.x * 8;
    int c = tid;

    // node_out = agg @ Won + bon ; +x1 residual
    {
        float acc[8] = {};
        for (int k = 0; k < DIMC; k++) {
            float wv = Won[k*DIMC + c];
            #pragma unroll
            for (int r = 0; r < 8; r++) acc[r] += g_agg[(row0+r)*DIMC + k] * wv;
        }
        #pragma unroll
        for (int r = 0; r < 8; r++)
            sx2[r][c] = acc[r] + bon[c] + g_x1[(row0+r)*DIMC + c];
    }
    __syncthreads();
    // LN3 in place (warp per row)
    {
        int w = tid >> 5, lane = tid & 31;
        float s = 0.f, sq = 0.f;
        #pragma unroll
        for (int u = 0; u < 8; u++) { float v = sx2[w][lane+u*32]; s += v; sq += v*v; }
        #pragma unroll
        for (int o = 16; o > 0; o >>= 1) { s += __shfl_xor_sync(~0u,s,o); sq += __shfl_xor_sync(~0u,sq,o); }
        float mean = s * (1.f/256.f);
        float rstd = rsqrtf(sq*(1.f/256.f) - mean*mean + EPSV);
        #pragma unroll
        for (int u = 0; u < 8; u++) {
            int cc = lane + u*32;
            sx2[w][cc] = (sx2[w][cc] - mean)*rstd*ln3s[cc] + ln3b[cc];
        }
    }
    __syncthreads();
    // hidden = relu(x2 @ w1 + b1)
    {
        float hacc[8][4] = {};
        for (int k = 0; k < DIMC; k++) {
            float xv[8];
            #pragma unroll
            for (int r = 0; r < 8; r++) xv[r] = sx2[r][k];
            #pragma unroll
            for (int m = 0; m < 4; m++) {
                float wv = w1[(size_t)k*HID + tid + m*256];
                #pragma unroll
                for (int r = 0; r < 8; r++) hacc[r][m] += xv[r]*wv;
            }
        }
        #pragma unroll
        for (int m = 0; m < 4; m++) {
            float bb = b1[tid + m*256];
            #pragma unroll
            for (int r = 0; r < 8; r++) sh[r][tid + m*256] = fmaxf(hacc[r][m] + bb, 0.f);
        }
    }
    __syncthreads();
    // mlp = h @ w2 + b2 ; +x2 residual
    {
        float acc[8] = {};
        for (int k = 0; k < HID; k++) {
            float wv = w2[k*DIMC + c];
            #pragma unroll
            for (int r = 0; r < 8; r++) acc[r] += sh[r][k]*wv;
        }
        __syncthreads();
        #pragma unroll
        for (int r = 0; r < 8; r++)
            sh[r][c] = acc[r] + b2[c] + sx2[r][c];
    }
    __syncthreads();
    // LN5 -> x_out
    {
        int w = tid >> 5, lane = tid & 31;
        float s = 0.f, sq = 0.f;
        #pragma unroll
        for (int u = 0; u < 8; u++) { float v = sh[w][lane+u*32]; s += v; sq += v*v; }
        #pragma unroll
        for (int o = 16; o > 0; o >>= 1) { s += __shfl_xor_sync(~0u,s,o); sq += __shfl_xor_sync(~0u,sq,o); }
        float mean = s * (1.f/256.f);
        float rstd = rsqrtf(sq*(1.f/256.f) - mean*mean + EPSV);
        #pragma unroll
        for (int u = 0; u < 8; u++) {
            int cc = lane + u*32;
            xout[(size_t)(row0+w)*DIMC + cc] = (sh[w][cc] - mean)*rstd*ln5s[cc] + ln5b[cc];
        }
    }
}

// ======================= launch =======================
extern "C" void kernel_launch(void* const* d_in, const int* in_sizes, int n_in,
                              void* d_out, int out_size)
{
    const float* x    = (const float*)d_in[0];
    const float* y    = (const float*)d_in[1];
    const float* Wq   = (const float*)d_in[2];  const float* bq  = (const float*)d_in[3];
    const float* Wk   = (const float*)d_in[4];  const float* bk  = (const float*)d_in[5];
    const float* Wv   = (const float*)d_in[6];  const float* bv  = (const float*)d_in[7];
    const float* We   = (const float*)d_in[8];  const float* be  = (const float*)d_in[9];
    const float* Woe  = (const float*)d_in[10]; const float* boe = (const float*)d_in[11];
    const float* Won  = (const float*)d_in[12]; const float* bon = (const float*)d_in[13];
    const float* m1w1 = (const float*)d_in[14]; const float* m1b1= (const float*)d_in[15];
    const float* m1w2 = (const float*)d_in[16]; const float* m1b2= (const float*)d_in[17];
    const float* m2w1 = (const float*)d_in[18]; const float* m2b1= (const float*)d_in[19];
    const float* m2w2 = (const float*)d_in[20]; const float* m2b2= (const float*)d_in[21];
    const float* ln1s = (const float*)d_in[22]; const float* ln1b= (const float*)d_in[23];
    const float* ln3s = (const float*)d_in[24]; const float* ln3b= (const float*)d_in[25];
    const float* ln4s = (const float*)d_in[26]; const float* ln4b= (const float*)d_in[27];
    const float* ln5s = (const float*)d_in[28]; const float* ln5b= (const float*)d_in[29];
    const float* ln6s = (const float*)d_in[30]; const float* ln6b= (const float*)d_in[31];

    float* out  = (float*)d_out;
    float* xout = out;                               // (8,128,256)
    float* yout = out + BAT*NTOK*DIMC;               // (8,128,128,256)

    int smem = (NTOK*SAS + NTOK*NTOK + NTOK*SATS + 16*NTOK + DIMC) * (int)sizeof(float);
    cudaFuncSetAttribute(edge_kernel, cudaFuncAttributeMaxDynamicSharedMemorySize, smem);

    node_pre_kernel<<<BAT*NTOK/4, 256>>>(x, Wq, bq, Wk, bk, Wv, bv, ln1s, ln1b);
    edge_kernel<<<BAT*NTOK, 256, smem>>>(y, We, be, Woe, boe,
                                         m2w1, m2b1, m2w2, m2b2,
                                         ln4s, ln4b, ln6s, ln6b, yout);
    node_post_kernel<<<BAT*NTOK/8, 256>>>(Won, bon, m1w1, m1b1, m1w2, m1b2,
                                          ln3s, ln3b, ln5s, ln5b, xout);
}